// round 12
// baseline (speedup 1.0000x reference)
#include <cuda_runtime.h>
#include <cuda_bf16.h>
#include <cstdint>

// Problem constants
#define BDIM 8
#define NPTS 8192
#define SPTS 2048
#define D1C  64
#define D2C  256
#define C1C  256
#define C2C  128
#define BNROWS (BDIM * NPTS)   // 65536
#define EPS_DIST 1e-10f
#define EPS_BN   1e-5f

// ---------------- scratch (device globals; no allocations allowed) ----------
__device__ float g_w[BNROWS * 3];
__device__ int   g_idx[BNROWS * 3];
__device__ float g_P2[BDIM * SPTS * C1C];      // 16384 x 256 fp32
__device__ float g_h1[BNROWS * C1C];           // 65536 x 256 fp32 (pre-BN h1)
__device__ float g_sum1[C1C], g_sq1[C1C], g_scale1[C1C], g_shift1[C1C];
__device__ float g_sum2[C2C], g_sq2[C2C], g_scale2[C2C], g_shift2[C2C];

// bf16 split operands (hi/lo)
__device__ __nv_bfloat16 g_p1h[BNROWS * D1C],      g_p1l[BNROWS * D1C];
__device__ __nv_bfloat16 g_p2h[BDIM*SPTS * D2C],   g_p2l[BDIM*SPTS * D2C];
__device__ __nv_bfloat16 g_w1h[C1C * (D1C+D2C)],   g_w1l[C1C * (D1C+D2C)];
__device__ __nv_bfloat16 g_w2h[C2C * C1C],         g_w2l[C2C * C1C];
__device__ __nv_bfloat16 g_a1h[BNROWS * C1C],      g_a1l[BNROWS * C1C];

// ---------------- helpers ----------------------------------------------------
__device__ __forceinline__ uint32_t smem_u32(const void* p) {
    uint32_t a;
    asm("{ .reg .u64 t; cvta.to.shared.u64 t, %1; cvt.u32.u64 %0, t; }"
        : "=r"(a) : "l"(p));
    return a;
}
__device__ __forceinline__ void cpasync16(uint32_t dst, const void* src) {
    asm volatile("cp.async.cg.shared.global [%0], [%1], 16;" :: "r"(dst), "l"(src));
}
#define CP_COMMIT() asm volatile("cp.async.commit_group;" ::: "memory")
#define CP_WAIT0()  asm volatile("cp.async.wait_group 0;" ::: "memory")
#define CP_WAIT1()  asm volatile("cp.async.wait_group 1;" ::: "memory")

__device__ __forceinline__ void mma16816(float* c, uint32_t a0, uint32_t a1,
                                         uint32_t a2, uint32_t a3,
                                         uint32_t b0, uint32_t b1) {
    asm volatile(
        "mma.sync.aligned.m16n8k16.row.col.f32.bf16.bf16.f32 "
        "{%0,%1,%2,%3}, {%4,%5,%6,%7}, {%8,%9}, {%0,%1,%2,%3};"
        : "+f"(c[0]), "+f"(c[1]), "+f"(c[2]), "+f"(c[3])
        : "r"(a0), "r"(a1), "r"(a2), "r"(a3), "r"(b0), "r"(b1));
}

// ---------------- prep: all fp32->bf16 hi/lo splits + stat zeroing ----------
__device__ __forceinline__ void split8(const float* __restrict__ src,
                                       __nv_bfloat16* __restrict__ hi,
                                       __nv_bfloat16* __restrict__ lo,
                                       int lb, int t) {
    const size_t i = ((size_t)lb * 256 + t) * 8;
    float4 a = *(const float4*)(src + i);
    float4 b = *(const float4*)(src + i + 4);
    float x[8] = {a.x, a.y, a.z, a.w, b.x, b.y, b.z, b.w};
    __nv_bfloat16 hv[8], lv[8];
    #pragma unroll
    for (int j = 0; j < 8; j++) {
        hv[j] = __float2bfloat16(x[j]);
        lv[j] = __float2bfloat16(x[j] - __bfloat162float(hv[j]));
    }
    *(uint4*)(hi + i) = *(uint4*)hv;
    *(uint4*)(lo + i) = *(uint4*)lv;
}

__global__ void prep_kernel(const float* __restrict__ points2,
                            const float* __restrict__ points1,
                            const float* __restrict__ W1,
                            const float* __restrict__ W2) {
    const int b = blockIdx.x, t = threadIdx.x;
    if (b < 2048)       split8(points2, g_p2h, g_p2l, b, t);
    else if (b < 4096)  split8(points1, g_p1h, g_p1l, b - 2048, t);
    else if (b < 4136)  split8(W1, g_w1h, g_w1l, b - 4096, t);
    else if (b < 4152)  split8(W2, g_w2h, g_w2l, b - 4136, t);
    else {
        if (t < C1C) { g_sum1[t] = 0.f; g_sq1[t] = 0.f; }
        if (t < C2C) { g_sum2[t] = 0.f; g_sq2[t] = 0.f; }
    }
}

// ---------------- kNN(3) + inverse-distance weights --------------------------
__global__ void knn_kernel(const float* __restrict__ xyz1,
                           const float* __restrict__ xyz2) {
    __shared__ float4 sp[SPTS];   // 32 KB
    const int b = blockIdx.y;
    const float* x2 = xyz2 + (size_t)b * SPTS * 3;
    for (int i = threadIdx.x; i < SPTS; i += blockDim.x)
        sp[i] = make_float4(x2[3 * i], x2[3 * i + 1], x2[3 * i + 2], 0.f);
    __syncthreads();

    const int n   = blockIdx.x * blockDim.x + threadIdx.x;
    const int row = b * NPTS + n;
    const float qx = xyz1[(size_t)row * 3 + 0];
    const float qy = xyz1[(size_t)row * 3 + 1];
    const float qz = xyz1[(size_t)row * 3 + 2];

    float d0 = 1e30f, d1 = 1e30f, d2v = 1e30f;
    int   i0 = 0,     i1 = 0,     i2 = 0;
    #pragma unroll 8
    for (int s = 0; s < SPTS; s++) {
        float4 p = sp[s];
        float dx = qx - p.x, dy = qy - p.y, dz = qz - p.z;
        float d = fmaf(dx, dx, fmaf(dy, dy, dz * dz));
        if (d < d2v) {
            if (d < d1) {
                d2v = d1; i2 = i1;
                if (d < d0) { d1 = d0; i1 = i0; d0 = d; i0 = s; }
                else        { d1 = d;  i1 = s; }
            } else { d2v = d; i2 = s; }
        }
    }
    d0  = fmaxf(d0,  EPS_DIST);
    d1  = fmaxf(d1,  EPS_DIST);
    d2v = fmaxf(d2v, EPS_DIST);
    float w0 = 1.f / d0, w1 = 1.f / d1, w2 = 1.f / d2v;
    float inv = 1.f / (w0 + w1 + w2);
    g_w[row * 3 + 0] = w0 * inv;
    g_w[row * 3 + 1] = w1 * inv;
    g_w[row * 3 + 2] = w2 * inv;
    g_idx[row * 3 + 0] = i0;
    g_idx[row * 3 + 1] = i1;
    g_idx[row * 3 + 2] = i2;
}

// a1 = relu(bn1(h1)) -> bf16 hi/lo
__global__ void conv_a1_kernel() {
    const size_t i = ((size_t)blockIdx.x * blockDim.x + threadIdx.x) * 8;
    const int c = (int)(i & (C1C - 1));
    float4 a = *(const float4*)(g_h1 + i);
    float4 b = *(const float4*)(g_h1 + i + 4);
    float x[8] = {a.x, a.y, a.z, a.w, b.x, b.y, b.z, b.w};
    __nv_bfloat16 hv[8], lv[8];
    #pragma unroll
    for (int j = 0; j < 8; j++) {
        float v = fmaxf(fmaf(x[j], g_scale1[c + j], g_shift1[c + j]), 0.f);
        hv[j] = __float2bfloat16(v);
        lv[j] = __float2bfloat16(v - __bfloat162float(hv[j]));
    }
    *(uint4*)(g_a1h + i) = *(uint4*)hv;
    *(uint4*)(g_a1l + i) = *(uint4*)lv;
}

// ---------------- HMMA split-bf16 GEMM, 2-stage cp.async pipeline ------------
// Block tile 64x128, BK=32, 8 warps (2x4), warp tile 32x32, 3 CTAs/SM target.
// SMEM stage layout (bytes): A-hi 0, A-lo 5120, B-hi 10240, B-lo 20480.
#define SROW 40            // smem row stride in bf16 (conflict-free)
#define STG_BYTES 30720
#define SMEM_GEMM (2 * STG_BYTES)

// EPI 0: P2 = points2 @ W1b^T          -> g_P2
// EPI 1: h1 = points1 @ W1a^T + gather -> g_h1   (+ fused BN1 stats)
// EPI 2: h2 = a1 @ W2^T                -> out    (+ fused BN2 stats)
template<int EPI>
__global__ void __launch_bounds__(256, 3) gemm_mma_kernel(float* __restrict__ outp) {
    extern __shared__ char dsm[];
    const int tid = threadIdx.x, wid = tid >> 5, lane = tid & 31;
    const int wm = wid >> 2, wn = wid & 3;          // warp grid 2x4
    const int g = lane >> 2, tig = lane & 3;
    const int m0 = blockIdx.x * 64, n0 = blockIdx.y * 128;

    const uint4 *A4h, *A4l, *B4h, *B4l;
    int sa8, sb8, bofs8, K;
    if (EPI == 0) {
        A4h = (const uint4*)g_p2h; A4l = (const uint4*)g_p2l; sa8 = D2C/8;
        B4h = (const uint4*)g_w1h; B4l = (const uint4*)g_w1l; sb8 = (D1C+D2C)/8;
        bofs8 = D1C/8; K = D2C;
    } else if (EPI == 1) {
        A4h = (const uint4*)g_p1h; A4l = (const uint4*)g_p1l; sa8 = D1C/8;
        B4h = (const uint4*)g_w1h; B4l = (const uint4*)g_w1l; sb8 = (D1C+D2C)/8;
        bofs8 = 0; K = D1C;
    } else {
        A4h = (const uint4*)g_a1h; A4l = (const uint4*)g_a1l; sa8 = C1C/8;
        B4h = (const uint4*)g_w2h; B4l = (const uint4*)g_w2l; sb8 = C1C/8;
        bofs8 = 0; K = C1C;
    }
    const int KB = K >> 5;
    const uint32_t sbase = smem_u32(dsm);

    // per stage: 64 A rows + 128 B rows, 4 uint4 per row, hi+lo each
    auto load_stage = [&](int st, int k8) {
        const uint32_t sa = sbase + st * STG_BYTES;
        #pragma unroll
        for (int u = tid; u < 768; u += 256) {
            const int row = u >> 2, kc = u & 3;
            if (row < 64) {
                const size_t ga = (size_t)(m0 + row) * sa8 + k8 + kc;
                const uint32_t so = sa + (uint32_t)(row * 5 + kc) * 16;
                cpasync16(so,        A4h + ga);
                cpasync16(so + 5120, A4l + ga);
            } else {
                const int rb = row - 64;
                const size_t gb = (size_t)(n0 + rb) * sb8 + bofs8 + k8 + kc;
                const uint32_t so = sa + 10240 + (uint32_t)(rb * 5 + kc) * 16;
                cpasync16(so,         B4h + gb);
                cpasync16(so + 10240, B4l + gb);
            }
        }
    };

    float acc[2][4][4];
    #pragma unroll
    for (int i = 0; i < 2; i++)
        #pragma unroll
        for (int j = 0; j < 4; j++)
            #pragma unroll
            for (int e = 0; e < 4; e++) acc[i][j][e] = 0.f;

    load_stage(0, 0);
    CP_COMMIT();

    for (int kb = 0; kb < KB; kb++) {
        if (kb + 1 < KB) {
            load_stage((kb + 1) & 1, (kb + 1) * 4);
            CP_COMMIT();
            CP_WAIT1();
        } else {
            CP_WAIT0();
        }
        __syncthreads();

        const __nv_bfloat16* sAh = (const __nv_bfloat16*)(dsm + (kb & 1) * STG_BYTES);
        const __nv_bfloat16* sAl = sAh + 2560;   // +5120 B
        const __nv_bfloat16* sBh = sAh + 5120;   // +10240 B
        const __nv_bfloat16* sBl = sAh + 10240;  // +20480 B

        #pragma unroll
        for (int kk = 0; kk < 32; kk += 16) {
            uint32_t ah[2][4], al[2][4];
            #pragma unroll
            for (int mi = 0; mi < 2; mi++) {
                const int r = wm * 32 + mi * 16 + g;
                const int o = r * SROW + kk + 2 * tig;
                ah[mi][0] = *(const uint32_t*)(sAh + o);
                ah[mi][1] = *(const uint32_t*)(sAh + o + 8 * SROW);
                ah[mi][2] = *(const uint32_t*)(sAh + o + 8);
                ah[mi][3] = *(const uint32_t*)(sAh + o + 8 * SROW + 8);
                al[mi][0] = *(const uint32_t*)(sAl + o);
                al[mi][1] = *(const uint32_t*)(sAl + o + 8 * SROW);
                al[mi][2] = *(const uint32_t*)(sAl + o + 8);
                al[mi][3] = *(const uint32_t*)(sAl + o + 8 * SROW + 8);
            }
            #pragma unroll
            for (int ni = 0; ni < 4; ni++) {
                const int nr = wn * 32 + ni * 8 + g;
                const int o = nr * SROW + kk + 2 * tig;
                uint32_t bh0 = *(const uint32_t*)(sBh + o);
                uint32_t bh1 = *(const uint32_t*)(sBh + o + 8);
                uint32_t bl0 = *(const uint32_t*)(sBl + o);
                uint32_t bl1 = *(const uint32_t*)(sBl + o + 8);
                #pragma unroll
                for (int mi = 0; mi < 2; mi++) {
                    mma16816(acc[mi][ni], ah[mi][0], ah[mi][1], ah[mi][2], ah[mi][3], bh0, bh1);
                    mma16816(acc[mi][ni], ah[mi][0], ah[mi][1], ah[mi][2], ah[mi][3], bl0, bl1);
                    mma16816(acc[mi][ni], al[mi][0], al[mi][1], al[mi][2], al[mi][3], bh0, bh1);
                }
            }
        }
        __syncthreads();
    }

    // ---------------- epilogue ----------------
    float* dst;
    int ldo;
    if (EPI == 0)      { dst = g_P2; ldo = C1C; }
    else if (EPI == 1) { dst = g_h1; ldo = C1C; }
    else               { dst = outp; ldo = C2C; }

    const float* P2b = nullptr;
    if (EPI == 1) P2b = g_P2 + (size_t)(m0 >> 13) * SPTS * C1C;

    float scol[8], qcol[8];   // fused BN stats partials (EPI 1/2)
    #pragma unroll
    for (int j = 0; j < 8; j++) { scol[j] = 0.f; qcol[j] = 0.f; }

    #pragma unroll
    for (int mi = 0; mi < 2; mi++) {
        #pragma unroll
        for (int rr = 0; rr < 2; rr++) {
            const int grow = m0 + wm * 32 + mi * 16 + g + rr * 8;
            float w0 = 0.f, w1 = 0.f, w2 = 0.f;
            const float *p0 = nullptr, *p1 = nullptr, *p2 = nullptr;
            if (EPI == 1) {
                w0 = g_w[grow * 3 + 0]; w1 = g_w[grow * 3 + 1]; w2 = g_w[grow * 3 + 2];
                p0 = P2b + (size_t)g_idx[grow * 3 + 0] * C1C;
                p1 = P2b + (size_t)g_idx[grow * 3 + 1] * C1C;
                p2 = P2b + (size_t)g_idx[grow * 3 + 2] * C1C;
            }
            #pragma unroll
            for (int ni = 0; ni < 4; ni++) {
                const int col = n0 + wn * 32 + ni * 8 + 2 * tig;
                float vx = acc[mi][ni][rr * 2 + 0];
                float vy = acc[mi][ni][rr * 2 + 1];
                if (EPI == 1) {
                    float2 q0 = *(const float2*)(p0 + col);
                    float2 q1 = *(const float2*)(p1 + col);
                    float2 q2 = *(const float2*)(p2 + col);
                    vx += w0 * q0.x + w1 * q1.x + w2 * q2.x;
                    vy += w0 * q0.y + w1 * q1.y + w2 * q2.y;
                }
                if (EPI != 0) {
                    scol[ni * 2 + 0] += vx; qcol[ni * 2 + 0] = fmaf(vx, vx, qcol[ni * 2 + 0]);
                    scol[ni * 2 + 1] += vy; qcol[ni * 2 + 1] = fmaf(vy, vy, qcol[ni * 2 + 1]);
                }
                *(float2*)(dst + (size_t)grow * ldo + col) = make_float2(vx, vy);
            }
        }
    }

    if (EPI != 0) {
        // reduce over g (lanes stride 4): xor 16/8/4 fold the 8 g-values
        #pragma unroll
        for (int j = 0; j < 8; j++) {
            #pragma unroll
            for (int m = 16; m >= 4; m >>= 1) {
                scol[j] += __shfl_xor_sync(0xffffffffu, scol[j], m);
                qcol[j] += __shfl_xor_sync(0xffffffffu, qcol[j], m);
            }
        }
        if (g == 0) {
            float* gs = (EPI == 1) ? g_sum1 : g_sum2;
            float* gq = (EPI == 1) ? g_sq1  : g_sq2;
            #pragma unroll
            for (int j = 0; j < 8; j++) {
                const int col = n0 + wn * 32 + (j >> 1) * 8 + 2 * tig + (j & 1);
                atomicAdd(&gs[col], scol[j]);
                atomicAdd(&gq[col], qcol[j]);
            }
        }
    }
}

// ---------------- fold BN into scale/shift -----------------------------------
__global__ void finalize_kernel(const float* __restrict__ gamma,
                                const float* __restrict__ beta, int which) {
    const int t = threadIdx.x;
    const float invM = 1.0f / (float)BNROWS;
    if (which == 0) {
        if (t < C1C) {
            float mean = g_sum1[t] * invM;
            float var  = g_sq1[t] * invM - mean * mean;
            float a    = gamma[t] * rsqrtf(var + EPS_BN);
            g_scale1[t] = a;
            g_shift1[t] = fmaf(-mean, a, beta[t]);
        }
    } else {
        if (t < C2C) {
            float mean = g_sum2[t] * invM;
            float var  = g_sq2[t] * invM - mean * mean;
            float a    = gamma[t] * rsqrtf(var + EPS_BN);
            g_scale2[t] = a;
            g_shift2[t] = fmaf(-mean, a, beta[t]);
        }
    }
}

// ---------------- out = relu(bn2(out)) in place ------------------------------
__global__ void apply_kernel(float* __restrict__ out) {
    const int i = blockIdx.x * blockDim.x + threadIdx.x;   // float4 index
    float4 v = ((float4*)out)[i];
    const int c = (i * 4) & (C2C - 1);
    v.x = fmaxf(fmaf(v.x, g_scale2[c + 0], g_shift2[c + 0]), 0.f);
    v.y = fmaxf(fmaf(v.y, g_scale2[c + 1], g_shift2[c + 1]), 0.f);
    v.z = fmaxf(fmaf(v.z, g_scale2[c + 2], g_shift2[c + 2]), 0.f);
    v.w = fmaxf(fmaf(v.w, g_scale2[c + 3], g_shift2[c + 3]), 0.f);
    ((float4*)out)[i] = v;
}

// ---------------- launch -----------------------------------------------------
extern "C" void kernel_launch(void* const* d_in, const int* in_sizes, int n_in,
                              void* d_out, int out_size) {
    const float* xyz1    = (const float*)d_in[0];
    const float* xyz2    = (const float*)d_in[1];
    const float* points1 = (const float*)d_in[2];
    const float* points2 = (const float*)d_in[3];
    const float* W1      = (const float*)d_in[4];
    const float* g1      = (const float*)d_in[5];
    const float* b1      = (const float*)d_in[6];
    const float* W2      = (const float*)d_in[7];
    const float* g2      = (const float*)d_in[8];
    const float* b2      = (const float*)d_in[9];
    float* out = (float*)d_out;
    (void)in_sizes; (void)n_in; (void)out_size;

    cudaFuncSetAttribute(gemm_mma_kernel<0>, cudaFuncAttributeMaxDynamicSharedMemorySize, SMEM_GEMM);
    cudaFuncSetAttribute(gemm_mma_kernel<1>, cudaFuncAttributeMaxDynamicSharedMemorySize, SMEM_GEMM);
    cudaFuncSetAttribute(gemm_mma_kernel<2>, cudaFuncAttributeMaxDynamicSharedMemorySize, SMEM_GEMM);

    prep_kernel<<<4153, 256>>>(points2, points1, W1, W2);                    // 0
    knn_kernel<<<dim3(NPTS / 256, BDIM), 256>>>(xyz1, xyz2);                 // 1
    gemm_mma_kernel<0><<<dim3(BDIM*SPTS/64, C1C/128), 256, SMEM_GEMM>>>(nullptr); // 2
    gemm_mma_kernel<1><<<dim3(BNROWS/64,    C1C/128), 256, SMEM_GEMM>>>(nullptr); // 3 (+stats1)
    finalize_kernel<<<1, 256>>>(g1, b1, 0);                                  // 4
    conv_a1_kernel<<<(BNROWS*C1C)/2048, 256>>>();                            // 5
    gemm_mma_kernel<2><<<dim3(BNROWS/64, C2C/128), 256, SMEM_GEMM>>>(out);   // 6 (+stats2)
    finalize_kernel<<<1, 256>>>(g2, b2, 1);                                  // 7
    apply_kernel<<<(BNROWS * C2C / 4) / 256, 256>>>(out);                    // 8
}

// round 13
// speedup vs baseline: 1.1854x; 1.1854x over previous
#include <cuda_runtime.h>
#include <cuda_bf16.h>
#include <cstdint>

// Problem constants
#define BDIM 8
#define NPTS 8192
#define SPTS 2048
#define D1C  64
#define D2C  256
#define C1C  256
#define C2C  128
#define BNROWS (BDIM * NPTS)   // 65536
#define EPS_DIST 1e-10f
#define EPS_BN   1e-5f

// ---------------- scratch (device globals; no allocations allowed) ----------
__device__ float g_w[BNROWS * 3];
__device__ int   g_idx[BNROWS * 3];
__device__ float g_P2[BDIM * SPTS * C1C];      // 16384 x 256 fp32
__device__ float g_h1[BNROWS * C1C];           // 65536 x 256 fp32 (pre-BN h1)
__device__ float g_sum1[C1C], g_sq1[C1C], g_scale1[C1C], g_shift1[C1C];
__device__ float g_sum2[C2C], g_sq2[C2C], g_scale2[C2C], g_shift2[C2C];

// bf16 split operands (hi/lo)
__device__ __nv_bfloat16 g_p1h[BNROWS * D1C],      g_p1l[BNROWS * D1C];
__device__ __nv_bfloat16 g_p2h[BDIM*SPTS * D2C],   g_p2l[BDIM*SPTS * D2C];
__device__ __nv_bfloat16 g_w1h[C1C * (D1C+D2C)],   g_w1l[C1C * (D1C+D2C)];
__device__ __nv_bfloat16 g_w2h[C2C * C1C],         g_w2l[C2C * C1C];

// ---------------- helpers ----------------------------------------------------
__device__ __forceinline__ uint32_t smem_u32(const void* p) {
    uint32_t a;
    asm("{ .reg .u64 t; cvta.to.shared.u64 t, %1; cvt.u32.u64 %0, t; }"
        : "=r"(a) : "l"(p));
    return a;
}
__device__ __forceinline__ void cpasync16(uint32_t dst, const void* src) {
    asm volatile("cp.async.cg.shared.global [%0], [%1], 16;" :: "r"(dst), "l"(src));
}
#define CP_COMMIT() asm volatile("cp.async.commit_group;" ::: "memory")
#define CP_WAIT0()  asm volatile("cp.async.wait_group 0;" ::: "memory")
#define CP_WAIT1()  asm volatile("cp.async.wait_group 1;" ::: "memory")

__device__ __forceinline__ void mma16816(float* c, uint32_t a0, uint32_t a1,
                                         uint32_t a2, uint32_t a3,
                                         uint32_t b0, uint32_t b1) {
    asm volatile(
        "mma.sync.aligned.m16n8k16.row.col.f32.bf16.bf16.f32 "
        "{%0,%1,%2,%3}, {%4,%5,%6,%7}, {%8,%9}, {%0,%1,%2,%3};"
        : "+f"(c[0]), "+f"(c[1]), "+f"(c[2]), "+f"(c[3])
        : "r"(a0), "r"(a1), "r"(a2), "r"(a3), "r"(b0), "r"(b1));
}

// ---------------- prep: all fp32->bf16 hi/lo splits + stat zeroing ----------
__device__ __forceinline__ void split8(const float* __restrict__ src,
                                       __nv_bfloat16* __restrict__ hi,
                                       __nv_bfloat16* __restrict__ lo,
                                       int lb, int t) {
    const size_t i = ((size_t)lb * 256 + t) * 8;
    float4 a = *(const float4*)(src + i);
    float4 b = *(const float4*)(src + i + 4);
    float x[8] = {a.x, a.y, a.z, a.w, b.x, b.y, b.z, b.w};
    __nv_bfloat16 hv[8], lv[8];
    #pragma unroll
    for (int j = 0; j < 8; j++) {
        hv[j] = __float2bfloat16(x[j]);
        lv[j] = __float2bfloat16(x[j] - __bfloat162float(hv[j]));
    }
    *(uint4*)(hi + i) = *(uint4*)hv;
    *(uint4*)(lo + i) = *(uint4*)lv;
}

__global__ void prep_kernel(const float* __restrict__ points2,
                            const float* __restrict__ points1,
                            const float* __restrict__ W1,
                            const float* __restrict__ W2) {
    const int b = blockIdx.x, t = threadIdx.x;
    if (b < 2048)       split8(points2, g_p2h, g_p2l, b, t);
    else if (b < 4096)  split8(points1, g_p1h, g_p1l, b - 2048, t);
    else if (b < 4136)  split8(W1, g_w1h, g_w1l, b - 4096, t);
    else if (b < 4152)  split8(W2, g_w2h, g_w2l, b - 4136, t);
    else {
        if (t < C1C) { g_sum1[t] = 0.f; g_sq1[t] = 0.f; }
        if (t < C2C) { g_sum2[t] = 0.f; g_sq2[t] = 0.f; }
    }
}

// ---------------- kNN(3) + inverse-distance weights --------------------------
__global__ void knn_kernel(const float* __restrict__ xyz1,
                           const float* __restrict__ xyz2) {
    __shared__ float4 sp[SPTS];   // 32 KB
    const int b = blockIdx.y;
    const float* x2 = xyz2 + (size_t)b * SPTS * 3;
    for (int i = threadIdx.x; i < SPTS; i += blockDim.x)
        sp[i] = make_float4(x2[3 * i], x2[3 * i + 1], x2[3 * i + 2], 0.f);
    __syncthreads();

    const int n   = blockIdx.x * blockDim.x + threadIdx.x;
    const int row = b * NPTS + n;
    const float qx = xyz1[(size_t)row * 3 + 0];
    const float qy = xyz1[(size_t)row * 3 + 1];
    const float qz = xyz1[(size_t)row * 3 + 2];

    float d0 = 1e30f, d1 = 1e30f, d2v = 1e30f;
    int   i0 = 0,     i1 = 0,     i2 = 0;
    #pragma unroll 8
    for (int s = 0; s < SPTS; s++) {
        float4 p = sp[s];
        float dx = qx - p.x, dy = qy - p.y, dz = qz - p.z;
        float d = fmaf(dx, dx, fmaf(dy, dy, dz * dz));
        if (d < d2v) {
            if (d < d1) {
                d2v = d1; i2 = i1;
                if (d < d0) { d1 = d0; i1 = i0; d0 = d; i0 = s; }
                else        { d1 = d;  i1 = s; }
            } else { d2v = d; i2 = s; }
        }
    }
    d0  = fmaxf(d0,  EPS_DIST);
    d1  = fmaxf(d1,  EPS_DIST);
    d2v = fmaxf(d2v, EPS_DIST);
    float w0 = 1.f / d0, w1 = 1.f / d1, w2 = 1.f / d2v;
    float inv = 1.f / (w0 + w1 + w2);
    g_w[row * 3 + 0] = w0 * inv;
    g_w[row * 3 + 1] = w1 * inv;
    g_w[row * 3 + 2] = w2 * inv;
    g_idx[row * 3 + 0] = i0;
    g_idx[row * 3 + 1] = i1;
    g_idx[row * 3 + 2] = i2;
}

// ---------------- HMMA split-bf16 GEMM, 2-stage cp.async pipeline ------------
// Block tile 128x128, BK=32, 8 warps (2x4), warp tile 64x32 (R10 config).
// Stage layout (bytes): A-hi 0, A-lo 10240, B-hi 20480, B-lo 30720.
#define SROW 40            // smem row stride in bf16 (conflict-free)
#define STG_BYTES 40960
#define SMEM_GEMM   (2 * STG_BYTES)
#define SMEM_GEMM2  (2 * STG_BYTES + 2048)   // + ss/sh tables (EPI 2)

// EPI 0: P2 = points2 @ W1b^T             -> g_P2
// EPI 1: h1 = points1 @ W1a^T + gather    -> g_h1   (+ fused BN1 stats)
// EPI 2: h2 = relu(bn1(h1)) @ W2^T        -> out    (+ fused BN2 stats;
//         BN1+ReLU+split fused into A-load from fp32 g_h1)
template<int EPI>
__global__ void __launch_bounds__(256, 2) gemm_mma_kernel(float* __restrict__ outp) {
    extern __shared__ char dsm[];
    const int tid = threadIdx.x, wid = tid >> 5, lane = tid & 31;
    const int wm = wid >> 2, wn = wid & 3;          // warp grid 2x4
    const int g = lane >> 2, tig = lane & 3;
    const int m0 = blockIdx.x * 128, n0 = blockIdx.y * 128;

    const uint4 *A4h, *A4l, *B4h, *B4l;
    int sa8, sb8, bofs8, K;
    if (EPI == 0) {
        A4h = (const uint4*)g_p2h; A4l = (const uint4*)g_p2l; sa8 = D2C/8;
        B4h = (const uint4*)g_w1h; B4l = (const uint4*)g_w1l; sb8 = (D1C+D2C)/8;
        bofs8 = D1C/8; K = D2C;
    } else if (EPI == 1) {
        A4h = (const uint4*)g_p1h; A4l = (const uint4*)g_p1l; sa8 = D1C/8;
        B4h = (const uint4*)g_w1h; B4l = (const uint4*)g_w1l; sb8 = (D1C+D2C)/8;
        bofs8 = 0; K = D1C;
    } else {
        A4h = nullptr; A4l = nullptr; sa8 = 0;      // A comes from g_h1 (fp32)
        B4h = (const uint4*)g_w2h; B4l = (const uint4*)g_w2l; sb8 = C1C/8;
        bofs8 = 0; K = C1C;
    }
    const int KB = K >> 5;
    const uint32_t sbase = smem_u32(dsm);

    float* ssm = (float*)(dsm + 2 * STG_BYTES);     // EPI2: ss[256], sh[256]
    if (EPI == 2) {
        ssm[tid]       = g_scale1[tid];
        ssm[256 + tid] = g_shift1[tid];
    }

    // cp.async loader: A+B for EPI 0/1; B only for EPI 2
    auto load_stage = [&](int st, int k8) {
        const uint32_t sa = sbase + st * STG_BYTES;
        #pragma unroll
        for (int u = tid; u < 512; u += 256) {
            const int row = u >> 2, kc = u & 3;
            const uint32_t so = (uint32_t)(row * 5 + kc) * 16;
            if (EPI != 2) {
                const size_t ga = (size_t)(m0 + row) * sa8 + k8 + kc;
                cpasync16(sa + so,         A4h + ga);
                cpasync16(sa + 10240 + so, A4l + ga);
            }
            const size_t gb = (size_t)(n0 + row) * sb8 + bofs8 + k8 + kc;
            cpasync16(sa + 20480 + so, B4h + gb);
            cpasync16(sa + 30720 + so, B4l + gb);
        }
    };

    // EPI2: A prefetch (fp32) + convert/store
    float4 aregs[4];
    auto ldgA = [&](int kb) {
        #pragma unroll
        for (int v = 0; v < 4; v++) {
            const int u = tid + v * 256;            // 0..1023
            const int row = u >> 3, c = (u & 7) * 4;
            aregs[v] = *(const float4*)(g_h1 + (size_t)(m0 + row) * C1C + kb * 32 + c);
        }
    };
    auto stsA = [&](int st, int kb) {
        char* sa = dsm + st * STG_BYTES;
        #pragma unroll
        for (int v = 0; v < 4; v++) {
            const int u = tid + v * 256;
            const int row = u >> 3, c4 = u & 7, c = c4 * 4;
            float4 a = aregs[v];
            const float4 sc = *(const float4*)(ssm + kb * 32 + c);
            const float4 sf = *(const float4*)(ssm + 256 + kb * 32 + c);
            float x0 = fmaxf(fmaf(a.x, sc.x, sf.x), 0.f);
            float x1 = fmaxf(fmaf(a.y, sc.y, sf.y), 0.f);
            float x2 = fmaxf(fmaf(a.z, sc.z, sf.z), 0.f);
            float x3 = fmaxf(fmaf(a.w, sc.w, sf.w), 0.f);
            __nv_bfloat16 h0 = __float2bfloat16(x0), h1 = __float2bfloat16(x1);
            __nv_bfloat16 h2 = __float2bfloat16(x2), h3 = __float2bfloat16(x3);
            __nv_bfloat16 l0 = __float2bfloat16(x0 - __bfloat162float(h0));
            __nv_bfloat16 l1 = __float2bfloat16(x1 - __bfloat162float(h1));
            __nv_bfloat16 l2 = __float2bfloat16(x2 - __bfloat162float(h2));
            __nv_bfloat16 l3 = __float2bfloat16(x3 - __bfloat162float(h3));
            uint2 hv, lv;
            hv.x = ((uint32_t)__bfloat16_as_ushort(h1) << 16) | __bfloat16_as_ushort(h0);
            hv.y = ((uint32_t)__bfloat16_as_ushort(h3) << 16) | __bfloat16_as_ushort(h2);
            lv.x = ((uint32_t)__bfloat16_as_ushort(l1) << 16) | __bfloat16_as_ushort(l0);
            lv.y = ((uint32_t)__bfloat16_as_ushort(l3) << 16) | __bfloat16_as_ushort(l2);
            const uint32_t so = (uint32_t)(row * 80 + c4 * 8);
            *(uint2*)(sa + so)         = hv;
            *(uint2*)(sa + 10240 + so) = lv;
        }
    };

    float acc[4][4][4];
    #pragma unroll
    for (int i = 0; i < 4; i++)
        #pragma unroll
        for (int j = 0; j < 4; j++)
            #pragma unroll
            for (int e = 0; e < 4; e++) acc[i][j][e] = 0.f;

    if (EPI == 2) ldgA(0);
    load_stage(0, 0);
    CP_COMMIT();
    if (EPI == 2) { __syncthreads(); stsA(0, 0); }   // ssm visible, then stage-0 A

    for (int kb = 0; kb < KB; kb++) {
        if (kb + 1 < KB) {
            if (EPI == 2) ldgA(kb + 1);
            load_stage((kb + 1) & 1, (kb + 1) * 4);
            CP_COMMIT();
            CP_WAIT1();
        } else {
            CP_WAIT0();
        }
        __syncthreads();

        const __nv_bfloat16* sAh = (const __nv_bfloat16*)(dsm + (kb & 1) * STG_BYTES);
        const __nv_bfloat16* sAl = sAh + 5120;
        const __nv_bfloat16* sBh = sAh + 10240;
        const __nv_bfloat16* sBl = sAh + 15360;

        #pragma unroll
        for (int kk = 0; kk < 32; kk += 16) {
            uint32_t ah[4][4], al[4][4];
            #pragma unroll
            for (int mi = 0; mi < 4; mi++) {
                const int r = wm * 64 + mi * 16 + g;
                const int o = r * SROW + kk + 2 * tig;
                ah[mi][0] = *(const uint32_t*)(sAh + o);
                ah[mi][1] = *(const uint32_t*)(sAh + o + 8 * SROW);
                ah[mi][2] = *(const uint32_t*)(sAh + o + 8);
                ah[mi][3] = *(const uint32_t*)(sAh + o + 8 * SROW + 8);
                al[mi][0] = *(const uint32_t*)(sAl + o);
                al[mi][1] = *(const uint32_t*)(sAl + o + 8 * SROW);
                al[mi][2] = *(const uint32_t*)(sAl + o + 8);
                al[mi][3] = *(const uint32_t*)(sAl + o + 8 * SROW + 8);
            }
            #pragma unroll
            for (int ni = 0; ni < 4; ni++) {
                const int nr = wn * 32 + ni * 8 + g;
                const int o = nr * SROW + kk + 2 * tig;
                uint32_t bh0 = *(const uint32_t*)(sBh + o);
                uint32_t bh1 = *(const uint32_t*)(sBh + o + 8);
                uint32_t bl0 = *(const uint32_t*)(sBl + o);
                uint32_t bl1 = *(const uint32_t*)(sBl + o + 8);
                #pragma unroll
                for (int mi = 0; mi < 4; mi++) {
                    mma16816(acc[mi][ni], ah[mi][0], ah[mi][1], ah[mi][2], ah[mi][3], bh0, bh1);
                    mma16816(acc[mi][ni], ah[mi][0], ah[mi][1], ah[mi][2], ah[mi][3], bl0, bl1);
                    mma16816(acc[mi][ni], al[mi][0], al[mi][1], al[mi][2], al[mi][3], bh0, bh1);
                }
            }
        }
        __syncthreads();
        if (EPI == 2 && kb + 1 < KB) stsA((kb + 1) & 1, kb + 1);
    }

    // ---------------- epilogue ----------------
    float* dst;
    int ldo;
    if (EPI == 0)      { dst = g_P2; ldo = C1C; }
    else if (EPI == 1) { dst = g_h1; ldo = C1C; }
    else               { dst = outp; ldo = C2C; }

    const float* P2b = nullptr;
    if (EPI == 1) P2b = g_P2 + (size_t)(m0 >> 13) * SPTS * C1C;

    float scol[8], qcol[8];   // fused BN stats partials (EPI 1/2)
    #pragma unroll
    for (int j = 0; j < 8; j++) { scol[j] = 0.f; qcol[j] = 0.f; }

    #pragma unroll
    for (int mi = 0; mi < 4; mi++) {
        #pragma unroll
        for (int rr = 0; rr < 2; rr++) {
            const int grow = m0 + wm * 64 + mi * 16 + g + rr * 8;
            float w0 = 0.f, w1 = 0.f, w2 = 0.f;
            const float *p0 = nullptr, *p1 = nullptr, *p2 = nullptr;
            if (EPI == 1) {
                w0 = g_w[grow * 3 + 0]; w1 = g_w[grow * 3 + 1]; w2 = g_w[grow * 3 + 2];
                p0 = P2b + (size_t)g_idx[grow * 3 + 0] * C1C;
                p1 = P2b + (size_t)g_idx[grow * 3 + 1] * C1C;
                p2 = P2b + (size_t)g_idx[grow * 3 + 2] * C1C;
            }
            #pragma unroll
            for (int ni = 0; ni < 4; ni++) {
                const int col = n0 + wn * 32 + ni * 8 + 2 * tig;
                float vx = acc[mi][ni][rr * 2 + 0];
                float vy = acc[mi][ni][rr * 2 + 1];
                if (EPI == 1) {
                    float2 q0 = *(const float2*)(p0 + col);
                    float2 q1 = *(const float2*)(p1 + col);
                    float2 q2 = *(const float2*)(p2 + col);
                    vx += w0 * q0.x + w1 * q1.x + w2 * q2.x;
                    vy += w0 * q0.y + w1 * q1.y + w2 * q2.y;
                }
                if (EPI != 0) {
                    scol[ni * 2 + 0] += vx; qcol[ni * 2 + 0] = fmaf(vx, vx, qcol[ni * 2 + 0]);
                    scol[ni * 2 + 1] += vy; qcol[ni * 2 + 1] = fmaf(vy, vy, qcol[ni * 2 + 1]);
                }
                *(float2*)(dst + (size_t)grow * ldo + col) = make_float2(vx, vy);
            }
        }
    }

    if (EPI != 0) {
        // reduce over g (lanes stride 4): xor 16/8/4 fold the 8 g-values
        #pragma unroll
        for (int j = 0; j < 8; j++) {
            #pragma unroll
            for (int m = 16; m >= 4; m >>= 1) {
                scol[j] += __shfl_xor_sync(0xffffffffu, scol[j], m);
                qcol[j] += __shfl_xor_sync(0xffffffffu, qcol[j], m);
            }
        }
        if (g == 0) {
            float* gs = (EPI == 1) ? g_sum1 : g_sum2;
            float* gq = (EPI == 1) ? g_sq1  : g_sq2;
            #pragma unroll
            for (int j = 0; j < 8; j++) {
                const int col = n0 + wn * 32 + (j >> 1) * 8 + 2 * tig + (j & 1);
                atomicAdd(&gs[col], scol[j]);
                atomicAdd(&gq[col], qcol[j]);
            }
        }
    }
}

// ---------------- fold BN into scale/shift -----------------------------------
__global__ void finalize_kernel(const float* __restrict__ gamma,
                                const float* __restrict__ beta, int which) {
    const int t = threadIdx.x;
    const float invM = 1.0f / (float)BNROWS;
    if (which == 0) {
        if (t < C1C) {
            float mean = g_sum1[t] * invM;
            float var  = g_sq1[t] * invM - mean * mean;
            float a    = gamma[t] * rsqrtf(var + EPS_BN);
            g_scale1[t] = a;
            g_shift1[t] = fmaf(-mean, a, beta[t]);
        }
    } else {
        if (t < C2C) {
            float mean = g_sum2[t] * invM;
            float var  = g_sq2[t] * invM - mean * mean;
            float a    = gamma[t] * rsqrtf(var + EPS_BN);
            g_scale2[t] = a;
            g_shift2[t] = fmaf(-mean, a, beta[t]);
        }
    }
}

// ---------------- out = relu(bn2(out)) in place ------------------------------
__global__ void apply_kernel(float* __restrict__ out) {
    const int i = blockIdx.x * blockDim.x + threadIdx.x;   // float4 index
    float4 v = ((float4*)out)[i];
    const int c = (i * 4) & (C2C - 1);
    v.x = fmaxf(fmaf(v.x, g_scale2[c + 0], g_shift2[c + 0]), 0.f);
    v.y = fmaxf(fmaf(v.y, g_scale2[c + 1], g_shift2[c + 1]), 0.f);
    v.z = fmaxf(fmaf(v.z, g_scale2[c + 2], g_shift2[c + 2]), 0.f);
    v.w = fmaxf(fmaf(v.w, g_scale2[c + 3], g_shift2[c + 3]), 0.f);
    ((float4*)out)[i] = v;
}

// ---------------- launch -----------------------------------------------------
extern "C" void kernel_launch(void* const* d_in, const int* in_sizes, int n_in,
                              void* d_out, int out_size) {
    const float* xyz1    = (const float*)d_in[0];
    const float* xyz2    = (const float*)d_in[1];
    const float* points1 = (const float*)d_in[2];
    const float* points2 = (const float*)d_in[3];
    const float* W1      = (const float*)d_in[4];
    const float* g1      = (const float*)d_in[5];
    const float* b1      = (const float*)d_in[6];
    const float* W2      = (const float*)d_in[7];
    const float* g2      = (const float*)d_in[8];
    const float* b2      = (const float*)d_in[9];
    float* out = (float*)d_out;
    (void)in_sizes; (void)n_in; (void)out_size;

    cudaFuncSetAttribute(gemm_mma_kernel<0>, cudaFuncAttributeMaxDynamicSharedMemorySize, SMEM_GEMM);
    cudaFuncSetAttribute(gemm_mma_kernel<1>, cudaFuncAttributeMaxDynamicSharedMemorySize, SMEM_GEMM);
    cudaFuncSetAttribute(gemm_mma_kernel<2>, cudaFuncAttributeMaxDynamicSharedMemorySize, SMEM_GEMM2);

    prep_kernel<<<4153, 256>>>(points2, points1, W1, W2);                    // 0
    knn_kernel<<<dim3(NPTS / 256, BDIM), 256>>>(xyz1, xyz2);                 // 1
    gemm_mma_kernel<0><<<dim3(BDIM*SPTS/128, C1C/128), 256, SMEM_GEMM>>>(nullptr); // 2
    gemm_mma_kernel<1><<<dim3(BNROWS/128,    C1C/128), 256, SMEM_GEMM>>>(nullptr); // 3 (+stats1)
    finalize_kernel<<<1, 256>>>(g1, b1, 0);                                  // 4
    gemm_mma_kernel<2><<<dim3(BNROWS/128, C2C/128), 256, SMEM_GEMM2>>>(out); // 5 (fused BN1+ReLU load, +stats2)
    finalize_kernel<<<1, 256>>>(g2, b2, 1);                                  // 6
    apply_kernel<<<(BNROWS * C2C / 4) / 256, 256>>>(out);                    // 7
}

// round 14
// speedup vs baseline: 1.1935x; 1.0069x over previous
#include <cuda_runtime.h>
#include <cuda_bf16.h>
#include <cstdint>

// Problem constants
#define BDIM 8
#define NPTS 8192
#define SPTS 2048
#define D1C  64
#define D2C  256
#define C1C  256
#define C2C  128
#define BNROWS (BDIM * NPTS)   // 65536
#define EPS_DIST 1e-10f
#define EPS_BN   1e-5f

// ---------------- scratch (device globals; no allocations allowed) ----------
__device__ float g_w[BNROWS * 3];
__device__ int   g_idx[BNROWS * 3];
__device__ float g_P2[BDIM * SPTS * C1C];      // 16384 x 256 fp32
__device__ float g_h1[BNROWS * C1C];           // 65536 x 256 fp32 (pre-BN h1)
__device__ float g_sum1[C1C], g_sq1[C1C], g_scale1[C1C], g_shift1[C1C];
__device__ float g_sum2[C2C], g_sq2[C2C], g_scale2[C2C], g_shift2[C2C];

// bf16 split operands (hi/lo) — weights only now
__device__ __nv_bfloat16 g_w1h[C1C * (D1C+D2C)],   g_w1l[C1C * (D1C+D2C)];
__device__ __nv_bfloat16 g_w2h[C2C * C1C],         g_w2l[C2C * C1C];

// ---------------- helpers ----------------------------------------------------
__device__ __forceinline__ uint32_t smem_u32(const void* p) {
    uint32_t a;
    asm("{ .reg .u64 t; cvta.to.shared.u64 t, %1; cvt.u32.u64 %0, t; }"
        : "=r"(a) : "l"(p));
    return a;
}
__device__ __forceinline__ void cpasync16(uint32_t dst, const void* src) {
    asm volatile("cp.async.cg.shared.global [%0], [%1], 16;" :: "r"(dst), "l"(src));
}
#define CP_COMMIT() asm volatile("cp.async.commit_group;" ::: "memory")
#define CP_WAIT0()  asm volatile("cp.async.wait_group 0;" ::: "memory")
#define CP_WAIT1()  asm volatile("cp.async.wait_group 1;" ::: "memory")

__device__ __forceinline__ void mma16816(float* c, uint32_t a0, uint32_t a1,
                                         uint32_t a2, uint32_t a3,
                                         uint32_t b0, uint32_t b1) {
    asm volatile(
        "mma.sync.aligned.m16n8k16.row.col.f32.bf16.bf16.f32 "
        "{%0,%1,%2,%3}, {%4,%5,%6,%7}, {%8,%9}, {%0,%1,%2,%3};"
        : "+f"(c[0]), "+f"(c[1]), "+f"(c[2]), "+f"(c[3])
        : "r"(a0), "r"(a1), "r"(a2), "r"(a3), "r"(b0), "r"(b1));
}

// ---------------- prep: weight fp32->bf16 hi/lo splits + stat zeroing -------
__device__ __forceinline__ void split8(const float* __restrict__ src,
                                       __nv_bfloat16* __restrict__ hi,
                                       __nv_bfloat16* __restrict__ lo,
                                       int lb, int t) {
    const size_t i = ((size_t)lb * 256 + t) * 8;
    float4 a = *(const float4*)(src + i);
    float4 b = *(const float4*)(src + i + 4);
    float x[8] = {a.x, a.y, a.z, a.w, b.x, b.y, b.z, b.w};
    __nv_bfloat16 hv[8], lv[8];
    #pragma unroll
    for (int j = 0; j < 8; j++) {
        hv[j] = __float2bfloat16(x[j]);
        lv[j] = __float2bfloat16(x[j] - __bfloat162float(hv[j]));
    }
    *(uint4*)(hi + i) = *(uint4*)hv;
    *(uint4*)(lo + i) = *(uint4*)lv;
}

__global__ void prep_kernel(const float* __restrict__ W1,
                            const float* __restrict__ W2) {
    const int b = blockIdx.x, t = threadIdx.x;
    if (b < 40)       split8(W1, g_w1h, g_w1l, b, t);
    else if (b < 56)  split8(W2, g_w2h, g_w2l, b - 40, t);
    else {
        if (t < C1C) { g_sum1[t] = 0.f; g_sq1[t] = 0.f; }
        if (t < C2C) { g_sum2[t] = 0.f; g_sq2[t] = 0.f; }
    }
}

// ---------------- kNN(3) + inverse-distance weights --------------------------
__global__ void knn_kernel(const float* __restrict__ xyz1,
                           const float* __restrict__ xyz2) {
    __shared__ float4 sp[SPTS];   // 32 KB
    const int b = blockIdx.y;
    const float* x2 = xyz2 + (size_t)b * SPTS * 3;
    for (int i = threadIdx.x; i < SPTS; i += blockDim.x)
        sp[i] = make_float4(x2[3 * i], x2[3 * i + 1], x2[3 * i + 2], 0.f);
    __syncthreads();

    const int n   = blockIdx.x * blockDim.x + threadIdx.x;
    const int row = b * NPTS + n;
    const float qx = xyz1[(size_t)row * 3 + 0];
    const float qy = xyz1[(size_t)row * 3 + 1];
    const float qz = xyz1[(size_t)row * 3 + 2];

    float d0 = 1e30f, d1 = 1e30f, d2v = 1e30f;
    int   i0 = 0,     i1 = 0,     i2 = 0;
    #pragma unroll 8
    for (int s = 0; s < SPTS; s++) {
        float4 p = sp[s];
        float dx = qx - p.x, dy = qy - p.y, dz = qz - p.z;
        float d = fmaf(dx, dx, fmaf(dy, dy, dz * dz));
        if (d < d2v) {
            if (d < d1) {
                d2v = d1; i2 = i1;
                if (d < d0) { d1 = d0; i1 = i0; d0 = d; i0 = s; }
                else        { d1 = d;  i1 = s; }
            } else { d2v = d; i2 = s; }
        }
    }
    d0  = fmaxf(d0,  EPS_DIST);
    d1  = fmaxf(d1,  EPS_DIST);
    d2v = fmaxf(d2v, EPS_DIST);
    float w0 = 1.f / d0, w1 = 1.f / d1, w2 = 1.f / d2v;
    float inv = 1.f / (w0 + w1 + w2);
    g_w[row * 3 + 0] = w0 * inv;
    g_w[row * 3 + 1] = w1 * inv;
    g_w[row * 3 + 2] = w2 * inv;
    g_idx[row * 3 + 0] = i0;
    g_idx[row * 3 + 1] = i1;
    g_idx[row * 3 + 2] = i2;
}

// ---------------- HMMA split-bf16 GEMM, 2-stage cp.async pipeline ------------
// Block tile 128x128, BK=32, 8 warps (2x4), warp tile 64x32.
// A operand read as fp32 (register prefetch -> split -> smem); B via cp.async.
// Stage layout (bytes): A-hi 0, A-lo 10240, B-hi 20480, B-lo 30720.
#define SROW 40            // smem row stride in bf16 (conflict-free)
#define STG_BYTES 40960
#define SMEM_GEMM   (2 * STG_BYTES)
#define SMEM_GEMM2  (2 * STG_BYTES + 2048)   // + ss/sh tables (EPI 2)

// EPI 0: P2 = points2 @ W1b^T             -> g_P2
// EPI 1: h1 = points1 @ W1a^T + gather    -> g_h1   (+ fused BN1 stats)
// EPI 2: h2 = relu(bn1(h1)) @ W2^T        -> out    (+ fused BN2 stats)
template<int EPI>
__global__ void __launch_bounds__(256, 2) gemm_mma_kernel(float* __restrict__ outp,
                                                          const float* __restrict__ Asrc) {
    extern __shared__ char dsm[];
    const int tid = threadIdx.x, wid = tid >> 5, lane = tid & 31;
    const int wm = wid >> 2, wn = wid & 3;          // warp grid 2x4
    const int g = lane >> 2, tig = lane & 3;
    const int m0 = blockIdx.x * 128, n0 = blockIdx.y * 128;

    constexpr int LDA = (EPI == 0) ? D2C : (EPI == 1) ? D1C : C1C;
    constexpr int K   = (EPI == 1) ? D1C : D2C;     // EPI2: C1C == D2C == 256
    constexpr int KB  = K >> 5;
    const uint4* B4h; const uint4* B4l;
    int sb8, bofs8;
    if (EPI == 0)      { B4h = (const uint4*)g_w1h; B4l = (const uint4*)g_w1l; sb8 = (D1C+D2C)/8; bofs8 = D1C/8; }
    else if (EPI == 1) { B4h = (const uint4*)g_w1h; B4l = (const uint4*)g_w1l; sb8 = (D1C+D2C)/8; bofs8 = 0; }
    else               { B4h = (const uint4*)g_w2h; B4l = (const uint4*)g_w2l; sb8 = C1C/8;       bofs8 = 0; }
    const uint32_t sbase = smem_u32(dsm);

    float* ssm = (float*)(dsm + 2 * STG_BYTES);     // EPI2: ss[256], sh[256]
    if (EPI == 2) {
        ssm[tid]       = g_scale1[tid];
        ssm[256 + tid] = g_shift1[tid];
    }

    // cp.async loader: B only
    auto load_stage = [&](int st, int k8) {
        const uint32_t sa = sbase + st * STG_BYTES;
        #pragma unroll
        for (int u = tid; u < 512; u += 256) {
            const int row = u >> 2, kc = u & 3;
            const uint32_t so = (uint32_t)(row * 5 + kc) * 16;
            const size_t gb = (size_t)(n0 + row) * sb8 + bofs8 + k8 + kc;
            cpasync16(sa + 20480 + so, B4h + gb);
            cpasync16(sa + 30720 + so, B4l + gb);
        }
    };

    // A prefetch (fp32) + convert/split/store
    float4 aregs[4];
    auto ldgA = [&](int kb) {
        #pragma unroll
        for (int v = 0; v < 4; v++) {
            const int u = tid + v * 256;            // 0..1023
            const int row = u >> 3, c = (u & 7) * 4;
            aregs[v] = *(const float4*)(Asrc + (size_t)(m0 + row) * LDA + kb * 32 + c);
        }
    };
    auto stsA = [&](int st, int kb) {
        char* sa = dsm + st * STG_BYTES;
        #pragma unroll
        for (int v = 0; v < 4; v++) {
            const int u = tid + v * 256;
            const int row = u >> 3, c4 = u & 7, c = c4 * 4;
            float4 a = aregs[v];
            float x0, x1, x2, x3;
            if (EPI == 2) {
                const float4 sc = *(const float4*)(ssm + kb * 32 + c);
                const float4 sf = *(const float4*)(ssm + 256 + kb * 32 + c);
                x0 = fmaxf(fmaf(a.x, sc.x, sf.x), 0.f);
                x1 = fmaxf(fmaf(a.y, sc.y, sf.y), 0.f);
                x2 = fmaxf(fmaf(a.z, sc.z, sf.z), 0.f);
                x3 = fmaxf(fmaf(a.w, sc.w, sf.w), 0.f);
            } else {
                x0 = a.x; x1 = a.y; x2 = a.z; x3 = a.w;
            }
            __nv_bfloat16 h0 = __float2bfloat16(x0), h1 = __float2bfloat16(x1);
            __nv_bfloat16 h2 = __float2bfloat16(x2), h3 = __float2bfloat16(x3);
            __nv_bfloat16 l0 = __float2bfloat16(x0 - __bfloat162float(h0));
            __nv_bfloat16 l1 = __float2bfloat16(x1 - __bfloat162float(h1));
            __nv_bfloat16 l2 = __float2bfloat16(x2 - __bfloat162float(h2));
            __nv_bfloat16 l3 = __float2bfloat16(x3 - __bfloat162float(h3));
            uint2 hv, lv;
            hv.x = ((uint32_t)__bfloat16_as_ushort(h1) << 16) | __bfloat16_as_ushort(h0);
            hv.y = ((uint32_t)__bfloat16_as_ushort(h3) << 16) | __bfloat16_as_ushort(h2);
            lv.x = ((uint32_t)__bfloat16_as_ushort(l1) << 16) | __bfloat16_as_ushort(l0);
            lv.y = ((uint32_t)__bfloat16_as_ushort(l3) << 16) | __bfloat16_as_ushort(l2);
            const uint32_t so = (uint32_t)(row * 80 + c4 * 8);
            *(uint2*)(sa + so)         = hv;
            *(uint2*)(sa + 10240 + so) = lv;
        }
    };

    float acc[4][4][4];
    #pragma unroll
    for (int i = 0; i < 4; i++)
        #pragma unroll
        for (int j = 0; j < 4; j++)
            #pragma unroll
            for (int e = 0; e < 4; e++) acc[i][j][e] = 0.f;

    ldgA(0);
    load_stage(0, 0);
    CP_COMMIT();
    if (EPI == 2) __syncthreads();                   // ssm visible before stsA
    stsA(0, 0);

    for (int kb = 0; kb < KB; kb++) {
        if (kb + 1 < KB) {
            ldgA(kb + 1);
            load_stage((kb + 1) & 1, (kb + 1) * 4);
            CP_COMMIT();
            CP_WAIT1();
        } else {
            CP_WAIT0();
        }
        __syncthreads();

        const __nv_bfloat16* sAh = (const __nv_bfloat16*)(dsm + (kb & 1) * STG_BYTES);
        const __nv_bfloat16* sAl = sAh + 5120;
        const __nv_bfloat16* sBh = sAh + 10240;
        const __nv_bfloat16* sBl = sAh + 15360;

        #pragma unroll
        for (int kk = 0; kk < 32; kk += 16) {
            uint32_t ah[4][4], al[4][4];
            #pragma unroll
            for (int mi = 0; mi < 4; mi++) {
                const int r = wm * 64 + mi * 16 + g;
                const int o = r * SROW + kk + 2 * tig;
                ah[mi][0] = *(const uint32_t*)(sAh + o);
                ah[mi][1] = *(const uint32_t*)(sAh + o + 8 * SROW);
                ah[mi][2] = *(const uint32_t*)(sAh + o + 8);
                ah[mi][3] = *(const uint32_t*)(sAh + o + 8 * SROW + 8);
                al[mi][0] = *(const uint32_t*)(sAl + o);
                al[mi][1] = *(const uint32_t*)(sAl + o + 8 * SROW);
                al[mi][2] = *(const uint32_t*)(sAl + o + 8);
                al[mi][3] = *(const uint32_t*)(sAl + o + 8 * SROW + 8);
            }
            #pragma unroll
            for (int ni = 0; ni < 4; ni++) {
                const int nr = wn * 32 + ni * 8 + g;
                const int o = nr * SROW + kk + 2 * tig;
                uint32_t bh0 = *(const uint32_t*)(sBh + o);
                uint32_t bh1 = *(const uint32_t*)(sBh + o + 8);
                uint32_t bl0 = *(const uint32_t*)(sBl + o);
                uint32_t bl1 = *(const uint32_t*)(sBl + o + 8);
                #pragma unroll
                for (int mi = 0; mi < 4; mi++) {
                    mma16816(acc[mi][ni], ah[mi][0], ah[mi][1], ah[mi][2], ah[mi][3], bh0, bh1);
                    mma16816(acc[mi][ni], ah[mi][0], ah[mi][1], ah[mi][2], ah[mi][3], bl0, bl1);
                    mma16816(acc[mi][ni], al[mi][0], al[mi][1], al[mi][2], al[mi][3], bh0, bh1);
                }
            }
        }
        __syncthreads();
        if (kb + 1 < KB) stsA((kb + 1) & 1, kb + 1);
    }

    // ---------------- epilogue ----------------
    float* dst;
    int ldo;
    if (EPI == 0)      { dst = g_P2; ldo = C1C; }
    else if (EPI == 1) { dst = g_h1; ldo = C1C; }
    else               { dst = outp; ldo = C2C; }

    const float* P2b = nullptr;
    if (EPI == 1) P2b = g_P2 + (size_t)(m0 >> 13) * SPTS * C1C;

    float scol[8], qcol[8];   // fused BN stats partials (EPI 1/2)
    #pragma unroll
    for (int j = 0; j < 8; j++) { scol[j] = 0.f; qcol[j] = 0.f; }

    #pragma unroll
    for (int mi = 0; mi < 4; mi++) {
        #pragma unroll
        for (int rr = 0; rr < 2; rr++) {
            const int grow = m0 + wm * 64 + mi * 16 + g + rr * 8;
            float w0 = 0.f, w1 = 0.f, w2 = 0.f;
            const float *p0 = nullptr, *p1 = nullptr, *p2 = nullptr;
            if (EPI == 1) {
                w0 = g_w[grow * 3 + 0]; w1 = g_w[grow * 3 + 1]; w2 = g_w[grow * 3 + 2];
                p0 = P2b + (size_t)g_idx[grow * 3 + 0] * C1C;
                p1 = P2b + (size_t)g_idx[grow * 3 + 1] * C1C;
                p2 = P2b + (size_t)g_idx[grow * 3 + 2] * C1C;
            }
            #pragma unroll
            for (int ni = 0; ni < 4; ni++) {
                const int col = n0 + wn * 32 + ni * 8 + 2 * tig;
                float vx = acc[mi][ni][rr * 2 + 0];
                float vy = acc[mi][ni][rr * 2 + 1];
                if (EPI == 1) {
                    float2 q0 = *(const float2*)(p0 + col);
                    float2 q1 = *(const float2*)(p1 + col);
                    float2 q2 = *(const float2*)(p2 + col);
                    vx += w0 * q0.x + w1 * q1.x + w2 * q2.x;
                    vy += w0 * q0.y + w1 * q1.y + w2 * q2.y;
                }
                if (EPI != 0) {
                    scol[ni * 2 + 0] += vx; qcol[ni * 2 + 0] = fmaf(vx, vx, qcol[ni * 2 + 0]);
                    scol[ni * 2 + 1] += vy; qcol[ni * 2 + 1] = fmaf(vy, vy, qcol[ni * 2 + 1]);
                }
                *(float2*)(dst + (size_t)grow * ldo + col) = make_float2(vx, vy);
            }
        }
    }

    if (EPI != 0) {
        // reduce over g (lanes stride 4): xor 16/8/4 fold the 8 g-values
        #pragma unroll
        for (int j = 0; j < 8; j++) {
            #pragma unroll
            for (int m = 16; m >= 4; m >>= 1) {
                scol[j] += __shfl_xor_sync(0xffffffffu, scol[j], m);
                qcol[j] += __shfl_xor_sync(0xffffffffu, qcol[j], m);
            }
        }
        if (g == 0) {
            float* gs = (EPI == 1) ? g_sum1 : g_sum2;
            float* gq = (EPI == 1) ? g_sq1  : g_sq2;
            #pragma unroll
            for (int j = 0; j < 8; j++) {
                const int col = n0 + wn * 32 + (j >> 1) * 8 + 2 * tig + (j & 1);
                atomicAdd(&gs[col], scol[j]);
                atomicAdd(&gq[col], qcol[j]);
            }
        }
    }
}

// ---------------- fold BN into scale/shift -----------------------------------
__global__ void finalize_kernel(const float* __restrict__ gamma,
                                const float* __restrict__ beta, int which) {
    const int t = threadIdx.x;
    const float invM = 1.0f / (float)BNROWS;
    if (which == 0) {
        if (t < C1C) {
            float mean = g_sum1[t] * invM;
            float var  = g_sq1[t] * invM - mean * mean;
            float a    = gamma[t] * rsqrtf(var + EPS_BN);
            g_scale1[t] = a;
            g_shift1[t] = fmaf(-mean, a, beta[t]);
        }
    } else {
        if (t < C2C) {
            float mean = g_sum2[t] * invM;
            float var  = g_sq2[t] * invM - mean * mean;
            float a    = gamma[t] * rsqrtf(var + EPS_BN);
            g_scale2[t] = a;
            g_shift2[t] = fmaf(-mean, a, beta[t]);
        }
    }
}

// ---------------- out = relu(bn2(out)) in place ------------------------------
__global__ void apply_kernel(float* __restrict__ out) {
    const int i = blockIdx.x * blockDim.x + threadIdx.x;   // float4 index
    float4 v = ((float4*)out)[i];
    const int c = (i * 4) & (C2C - 1);
    v.x = fmaxf(fmaf(v.x, g_scale2[c + 0], g_shift2[c + 0]), 0.f);
    v.y = fmaxf(fmaf(v.y, g_scale2[c + 1], g_shift2[c + 1]), 0.f);
    v.z = fmaxf(fmaf(v.z, g_scale2[c + 2], g_shift2[c + 2]), 0.f);
    v.w = fmaxf(fmaf(v.w, g_scale2[c + 3], g_shift2[c + 3]), 0.f);
    ((float4*)out)[i] = v;
}

// ---------------- launch -----------------------------------------------------
extern "C" void kernel_launch(void* const* d_in, const int* in_sizes, int n_in,
                              void* d_out, int out_size) {
    const float* xyz1    = (const float*)d_in[0];
    const float* xyz2    = (const float*)d_in[1];
    const float* points1 = (const float*)d_in[2];
    const float* points2 = (const float*)d_in[3];
    const float* W1      = (const float*)d_in[4];
    const float* g1      = (const float*)d_in[5];
    const float* b1      = (const float*)d_in[6];
    const float* W2      = (const float*)d_in[7];
    const float* g2      = (const float*)d_in[8];
    const float* b2      = (const float*)d_in[9];
    float* out = (float*)d_out;
    (void)in_sizes; (void)n_in; (void)out_size;

    float* h1p;
    cudaGetSymbolAddress((void**)&h1p, g_h1);

    cudaFuncSetAttribute(gemm_mma_kernel<0>, cudaFuncAttributeMaxDynamicSharedMemorySize, SMEM_GEMM);
    cudaFuncSetAttribute(gemm_mma_kernel<1>, cudaFuncAttributeMaxDynamicSharedMemorySize, SMEM_GEMM);
    cudaFuncSetAttribute(gemm_mma_kernel<2>, cudaFuncAttributeMaxDynamicSharedMemorySize, SMEM_GEMM2);

    prep_kernel<<<57, 256>>>(W1, W2);                                        // 0
    knn_kernel<<<dim3(NPTS / 256, BDIM), 256>>>(xyz1, xyz2);                 // 1
    gemm_mma_kernel<0><<<dim3(BDIM*SPTS/128, C1C/128), 256, SMEM_GEMM>>>(nullptr, points2); // 2
    gemm_mma_kernel<1><<<dim3(BNROWS/128,    C1C/128), 256, SMEM_GEMM>>>(nullptr, points1); // 3 (+stats1)
    finalize_kernel<<<1, 256>>>(g1, b1, 0);                                  // 4
    gemm_mma_kernel<2><<<dim3(BNROWS/128, C2C/128), 256, SMEM_GEMM2>>>(out, h1p); // 5 (fused BN1 load, +stats2)
    finalize_kernel<<<1, 256>>>(g2, b2, 1);                                  // 6
    apply_kernel<<<(BNROWS * C2C / 4) / 256, 256>>>(out);                    // 7
}

// round 16
// speedup vs baseline: 1.2205x; 1.0226x over previous
#include <cuda_runtime.h>
#include <cuda_bf16.h>
#include <cstdint>

// Problem constants
#define BDIM 8
#define NPTS 8192
#define SPTS 2048
#define D1C  64
#define D2C  256
#define C1C  256
#define C2C  128
#define BNROWS (BDIM * NPTS)   // 65536
#define EPS_DIST 1e-10f
#define EPS_BN   1e-5f

// ---------------- scratch (device globals; no allocations allowed) ----------
__device__ float g_w[BNROWS * 3];
__device__ int   g_idx[BNROWS * 3];
__device__ float g_P2[BDIM * SPTS * C1C];      // 16384 x 256 fp32
__device__ float g_h1[BNROWS * C1C];           // 65536 x 256 fp32 (pre-BN h1)
__device__ float g_sum1[C1C], g_sq1[C1C], g_scale1[C1C], g_shift1[C1C];
__device__ float g_sum2[C2C], g_sq2[C2C], g_scale2[C2C], g_shift2[C2C];

// bf16 split operands (hi/lo) — weights only
__device__ __nv_bfloat16 g_w1h[C1C * (D1C+D2C)],   g_w1l[C1C * (D1C+D2C)];
__device__ __nv_bfloat16 g_w2h[C2C * C1C],         g_w2l[C2C * C1C];

// ---------------- helpers ----------------------------------------------------
__device__ __forceinline__ uint32_t smem_u32(const void* p) {
    uint32_t a;
    asm("{ .reg .u64 t; cvta.to.shared.u64 t, %1; cvt.u32.u64 %0, t; }"
        : "=r"(a) : "l"(p));
    return a;
}
__device__ __forceinline__ void cpasync16(uint32_t dst, const void* src) {
    asm volatile("cp.async.cg.shared.global [%0], [%1], 16;" :: "r"(dst), "l"(src));
}
#define CP_COMMIT() asm volatile("cp.async.commit_group;" ::: "memory")
#define CP_WAIT0()  asm volatile("cp.async.wait_group 0;" ::: "memory")
#define CP_WAIT1()  asm volatile("cp.async.wait_group 1;" ::: "memory")

__device__ __forceinline__ void mma16816(float* c, uint32_t a0, uint32_t a1,
                                         uint32_t a2, uint32_t a3,
                                         uint32_t b0, uint32_t b1) {
    asm volatile(
        "mma.sync.aligned.m16n8k16.row.col.f32.bf16.bf16.f32 "
        "{%0,%1,%2,%3}, {%4,%5,%6,%7}, {%8,%9}, {%0,%1,%2,%3};"
        : "+f"(c[0]), "+f"(c[1]), "+f"(c[2]), "+f"(c[3])
        : "r"(a0), "r"(a1), "r"(a2), "r"(a3), "r"(b0), "r"(b1));
}

// ---------------- prep: weight fp32->bf16 hi/lo splits + stat zeroing -------
__device__ __forceinline__ void split8(const float* __restrict__ src,
                                       __nv_bfloat16* __restrict__ hi,
                                       __nv_bfloat16* __restrict__ lo,
                                       int lb, int t) {
    const size_t i = ((size_t)lb * 256 + t) * 8;
    float4 a = *(const float4*)(src + i);
    float4 b = *(const float4*)(src + i + 4);
    float x[8] = {a.x, a.y, a.z, a.w, b.x, b.y, b.z, b.w};
    __nv_bfloat16 hv[8], lv[8];
    #pragma unroll
    for (int j = 0; j < 8; j++) {
        hv[j] = __float2bfloat16(x[j]);
        lv[j] = __float2bfloat16(x[j] - __bfloat162float(hv[j]));
    }
    *(uint4*)(hi + i) = *(uint4*)hv;
    *(uint4*)(lo + i) = *(uint4*)lv;
}

__global__ void prep_kernel(const float* __restrict__ W1,
                            const float* __restrict__ W2) {
    const int b = blockIdx.x, t = threadIdx.x;
    if (b < 40)       split8(W1, g_w1h, g_w1l, b, t);
    else if (b < 56)  split8(W2, g_w2h, g_w2l, b - 40, t);
    else {
        if (t < C1C) { g_sum1[t] = 0.f; g_sq1[t] = 0.f; }
        if (t < C2C) { g_sum2[t] = 0.f; g_sq2[t] = 0.f; }
    }
}

// ---------------- kNN(3) body (uses dynamic smem) ----------------------------
__device__ __forceinline__ void knn_body(const float* __restrict__ xyz1,
                                         const float* __restrict__ xyz2,
                                         int qb, char* dsm) {
    float4* sp = (float4*)dsm;                  // 32 KB of the dynamic pool
    const int b  = qb >> 5;                     // 32 blocks per batch
    const int bx = qb & 31;
    const float* x2 = xyz2 + (size_t)b * SPTS * 3;
    for (int i = threadIdx.x; i < SPTS; i += 256)
        sp[i] = make_float4(x2[3 * i], x2[3 * i + 1], x2[3 * i + 2], 0.f);
    __syncthreads();

    const int n   = bx * 256 + threadIdx.x;
    const int row = b * NPTS + n;
    const float qx = xyz1[(size_t)row * 3 + 0];
    const float qy = xyz1[(size_t)row * 3 + 1];
    const float qz = xyz1[(size_t)row * 3 + 2];

    float d0 = 1e30f, d1 = 1e30f, d2v = 1e30f;
    int   i0 = 0,     i1 = 0,     i2 = 0;
    #pragma unroll 8
    for (int s = 0; s < SPTS; s++) {
        float4 p = sp[s];
        float dx = qx - p.x, dy = qy - p.y, dz = qz - p.z;
        float d = fmaf(dx, dx, fmaf(dy, dy, dz * dz));
        if (d < d2v) {
            if (d < d1) {
                d2v = d1; i2 = i1;
                if (d < d0) { d1 = d0; i1 = i0; d0 = d; i0 = s; }
                else        { d1 = d;  i1 = s; }
            } else { d2v = d; i2 = s; }
        }
    }
    d0  = fmaxf(d0,  EPS_DIST);
    d1  = fmaxf(d1,  EPS_DIST);
    d2v = fmaxf(d2v, EPS_DIST);
    float w0 = 1.f / d0, w1 = 1.f / d1, w2 = 1.f / d2v;
    float inv = 1.f / (w0 + w1 + w2);
    g_w[row * 3 + 0] = w0 * inv;
    g_w[row * 3 + 1] = w1 * inv;
    g_w[row * 3 + 2] = w2 * inv;
    g_idx[row * 3 + 0] = i0;
    g_idx[row * 3 + 1] = i1;
    g_idx[row * 3 + 2] = i2;
}

// ---------------- HMMA split-bf16 GEMM body, 2-stage cp.async pipeline -------
// Block tile 128x128, BK=32, 8 warps (2x4), warp tile 64x32.
// A operand read as fp32 (register prefetch -> split -> smem); B via cp.async.
// Stage layout (bytes): A-hi 0, A-lo 10240, B-hi 20480, B-lo 30720.
#define SROW 40            // smem row stride in bf16 (conflict-free)
#define STG_BYTES 40960
#define SMEM_GEMM   (2 * STG_BYTES)
#define SMEM_GEMM2  (2 * STG_BYTES + 2048)   // + ss/sh tables (EPI 2)

// EPI 0: P2 = points2 @ W1b^T             -> g_P2
// EPI 1: h1 = points1 @ W1a^T + gather    -> g_h1   (+ fused BN1 stats)
// EPI 2: h2 = relu(bn1(h1)) @ W2^T        -> out    (+ fused BN2 stats)
template<int EPI>
__device__ __forceinline__ void gemm_body(float* __restrict__ outp,
                                          const float* __restrict__ Asrc,
                                          const int m0, const int n0,
                                          char* dsm) {
    const int tid = threadIdx.x, wid = tid >> 5, lane = tid & 31;
    const int wm = wid >> 2, wn = wid & 3;          // warp grid 2x4
    const int g = lane >> 2, tig = lane & 3;

    constexpr int LDA = (EPI == 0) ? D2C : (EPI == 1) ? D1C : C1C;
    constexpr int K   = (EPI == 1) ? D1C : D2C;
    constexpr int KB  = K >> 5;
    const uint4* B4h; const uint4* B4l;
    int sb8, bofs8;
    if (EPI == 0)      { B4h = (const uint4*)g_w1h; B4l = (const uint4*)g_w1l; sb8 = (D1C+D2C)/8; bofs8 = D1C/8; }
    else if (EPI == 1) { B4h = (const uint4*)g_w1h; B4l = (const uint4*)g_w1l; sb8 = (D1C+D2C)/8; bofs8 = 0; }
    else               { B4h = (const uint4*)g_w2h; B4l = (const uint4*)g_w2l; sb8 = C1C/8;       bofs8 = 0; }
    const uint32_t sbase = smem_u32(dsm);

    float* ssm = (float*)(dsm + 2 * STG_BYTES);     // EPI2: ss[256], sh[256]
    if (EPI == 2) {
        ssm[tid]       = g_scale1[tid];
        ssm[256 + tid] = g_shift1[tid];
    }

    // cp.async loader: B only
    auto load_stage = [&](int st, int k8) {
        const uint32_t sa = sbase + st * STG_BYTES;
        #pragma unroll
        for (int u = tid; u < 512; u += 256) {
            const int row = u >> 2, kc = u & 3;
            const uint32_t so = (uint32_t)(row * 5 + kc) * 16;
            const size_t gb = (size_t)(n0 + row) * sb8 + bofs8 + k8 + kc;
            cpasync16(sa + 20480 + so, B4h + gb);
            cpasync16(sa + 30720 + so, B4l + gb);
        }
    };

    // A prefetch (fp32) + convert/split/store
    float4 aregs[4];
    auto ldgA = [&](int kb) {
        #pragma unroll
        for (int v = 0; v < 4; v++) {
            const int u = tid + v * 256;            // 0..1023
            const int row = u >> 3, c = (u & 7) * 4;
            aregs[v] = *(const float4*)(Asrc + (size_t)(m0 + row) * LDA + kb * 32 + c);
        }
    };
    auto stsA = [&](int st, int kb) {
        char* sa = dsm + st * STG_BYTES;
        #pragma unroll
        for (int v = 0; v < 4; v++) {
            const int u = tid + v * 256;
            const int row = u >> 3, c4 = u & 7, c = c4 * 4;
            float4 a = aregs[v];
            float x0, x1, x2, x3;
            if (EPI == 2) {
                const float4 sc = *(const float4*)(ssm + kb * 32 + c);
                const float4 sf = *(const float4*)(ssm + 256 + kb * 32 + c);
                x0 = fmaxf(fmaf(a.x, sc.x, sf.x), 0.f);
                x1 = fmaxf(fmaf(a.y, sc.y, sf.y), 0.f);
                x2 = fmaxf(fmaf(a.z, sc.z, sf.z), 0.f);
                x3 = fmaxf(fmaf(a.w, sc.w, sf.w), 0.f);
            } else {
                x0 = a.x; x1 = a.y; x2 = a.z; x3 = a.w;
            }
            __nv_bfloat16 h0 = __float2bfloat16(x0), h1 = __float2bfloat16(x1);
            __nv_bfloat16 h2 = __float2bfloat16(x2), h3 = __float2bfloat16(x3);
            __nv_bfloat16 l0 = __float2bfloat16(x0 - __bfloat162float(h0));
            __nv_bfloat16 l1 = __float2bfloat16(x1 - __bfloat162float(h1));
            __nv_bfloat16 l2 = __float2bfloat16(x2 - __bfloat162float(h2));
            __nv_bfloat16 l3 = __float2bfloat16(x3 - __bfloat162float(h3));
            uint2 hv, lv;
            hv.x = ((uint32_t)__bfloat16_as_ushort(h1) << 16) | __bfloat16_as_ushort(h0);
            hv.y = ((uint32_t)__bfloat16_as_ushort(h3) << 16) | __bfloat16_as_ushort(h2);
            lv.x = ((uint32_t)__bfloat16_as_ushort(l1) << 16) | __bfloat16_as_ushort(l0);
            lv.y = ((uint32_t)__bfloat16_as_ushort(l3) << 16) | __bfloat16_as_ushort(l2);
            const uint32_t so = (uint32_t)(row * 80 + c4 * 8);
            *(uint2*)(sa + so)         = hv;
            *(uint2*)(sa + 10240 + so) = lv;
        }
    };

    float acc[4][4][4];
    #pragma unroll
    for (int i = 0; i < 4; i++)
        #pragma unroll
        for (int j = 0; j < 4; j++)
            #pragma unroll
            for (int e = 0; e < 4; e++) acc[i][j][e] = 0.f;

    ldgA(0);
    load_stage(0, 0);
    CP_COMMIT();
    if (EPI == 2) __syncthreads();                   // ssm visible before stsA
    stsA(0, 0);

    for (int kb = 0; kb < KB; kb++) {
        if (kb + 1 < KB) {
            ldgA(kb + 1);
            load_stage((kb + 1) & 1, (kb + 1) * 4);
            CP_COMMIT();
            CP_WAIT1();
        } else {
            CP_WAIT0();
        }
        __syncthreads();

        const __nv_bfloat16* sAh = (const __nv_bfloat16*)(dsm + (kb & 1) * STG_BYTES);
        const __nv_bfloat16* sAl = sAh + 5120;
        const __nv_bfloat16* sBh = sAh + 10240;
        const __nv_bfloat16* sBl = sAh + 15360;

        #pragma unroll
        for (int kk = 0; kk < 32; kk += 16) {
            uint32_t ah[4][4], al[4][4];
            #pragma unroll
            for (int mi = 0; mi < 4; mi++) {
                const int r = wm * 64 + mi * 16 + g;
                const int o = r * SROW + kk + 2 * tig;
                ah[mi][0] = *(const uint32_t*)(sAh + o);
                ah[mi][1] = *(const uint32_t*)(sAh + o + 8 * SROW);
                ah[mi][2] = *(const uint32_t*)(sAh + o + 8);
                ah[mi][3] = *(const uint32_t*)(sAh + o + 8 * SROW + 8);
                al[mi][0] = *(const uint32_t*)(sAl + o);
                al[mi][1] = *(const uint32_t*)(sAl + o + 8 * SROW);
                al[mi][2] = *(const uint32_t*)(sAl + o + 8);
                al[mi][3] = *(const uint32_t*)(sAl + o + 8 * SROW + 8);
            }
            #pragma unroll
            for (int ni = 0; ni < 4; ni++) {
                const int nr = wn * 32 + ni * 8 + g;
                const int o = nr * SROW + kk + 2 * tig;
                uint32_t bh0 = *(const uint32_t*)(sBh + o);
                uint32_t bh1 = *(const uint32_t*)(sBh + o + 8);
                uint32_t bl0 = *(const uint32_t*)(sBl + o);
                uint32_t bl1 = *(const uint32_t*)(sBl + o + 8);
                #pragma unroll
                for (int mi = 0; mi < 4; mi++) {
                    mma16816(acc[mi][ni], ah[mi][0], ah[mi][1], ah[mi][2], ah[mi][3], bh0, bh1);
                    mma16816(acc[mi][ni], ah[mi][0], ah[mi][1], ah[mi][2], ah[mi][3], bl0, bl1);
                    mma16816(acc[mi][ni], al[mi][0], al[mi][1], al[mi][2], al[mi][3], bh0, bh1);
                }
            }
        }
        __syncthreads();
        if (kb + 1 < KB) stsA((kb + 1) & 1, kb + 1);
    }

    // ---------------- epilogue ----------------
    float* dst;
    int ldo;
    if (EPI == 0)      { dst = g_P2; ldo = C1C; }
    else if (EPI == 1) { dst = g_h1; ldo = C1C; }
    else               { dst = outp; ldo = C2C; }

    const float* P2b = nullptr;
    if (EPI == 1) P2b = g_P2 + (size_t)(m0 >> 13) * SPTS * C1C;

    float scol[8], qcol[8];   // fused BN stats partials (EPI 1/2)
    #pragma unroll
    for (int j = 0; j < 8; j++) { scol[j] = 0.f; qcol[j] = 0.f; }

    #pragma unroll
    for (int mi = 0; mi < 4; mi++) {
        #pragma unroll
        for (int rr = 0; rr < 2; rr++) {
            const int grow = m0 + wm * 64 + mi * 16 + g + rr * 8;
            float w0 = 0.f, w1 = 0.f, w2 = 0.f;
            const float *p0 = nullptr, *p1 = nullptr, *p2 = nullptr;
            if (EPI == 1) {
                w0 = g_w[grow * 3 + 0]; w1 = g_w[grow * 3 + 1]; w2 = g_w[grow * 3 + 2];
                p0 = P2b + (size_t)g_idx[grow * 3 + 0] * C1C;
                p1 = P2b + (size_t)g_idx[grow * 3 + 1] * C1C;
                p2 = P2b + (size_t)g_idx[grow * 3 + 2] * C1C;
            }
            #pragma unroll
            for (int ni = 0; ni < 4; ni++) {
                const int col = n0 + wn * 32 + ni * 8 + 2 * tig;
                float vx = acc[mi][ni][rr * 2 + 0];
                float vy = acc[mi][ni][rr * 2 + 1];
                if (EPI == 1) {
                    float2 q0 = *(const float2*)(p0 + col);
                    float2 q1 = *(const float2*)(p1 + col);
                    float2 q2 = *(const float2*)(p2 + col);
                    vx += w0 * q0.x + w1 * q1.x + w2 * q2.x;
                    vy += w0 * q0.y + w1 * q1.y + w2 * q2.y;
                }
                if (EPI != 0) {
                    scol[ni * 2 + 0] += vx; qcol[ni * 2 + 0] = fmaf(vx, vx, qcol[ni * 2 + 0]);
                    scol[ni * 2 + 1] += vy; qcol[ni * 2 + 1] = fmaf(vy, vy, qcol[ni * 2 + 1]);
                }
                *(float2*)(dst + (size_t)grow * ldo + col) = make_float2(vx, vy);
            }
        }
    }

    if (EPI != 0) {
        // reduce over g (lanes stride 4): xor 16/8/4 fold the 8 g-values
        #pragma unroll
        for (int j = 0; j < 8; j++) {
            #pragma unroll
            for (int m = 16; m >= 4; m >>= 1) {
                scol[j] += __shfl_xor_sync(0xffffffffu, scol[j], m);
                qcol[j] += __shfl_xor_sync(0xffffffffu, qcol[j], m);
            }
        }
        if (g == 0) {
            float* gs = (EPI == 1) ? g_sum1 : g_sum2;
            float* gq = (EPI == 1) ? g_sq1  : g_sq2;
            #pragma unroll
            for (int j = 0; j < 8; j++) {
                const int col = n0 + wn * 32 + (j >> 1) * 8 + 2 * tig + (j & 1);
                atomicAdd(&gs[col], scol[j]);
                atomicAdd(&gq[col], qcol[j]);
            }
        }
    }
}

// ---------------- fused launch 0: gemm0 tiles + knn, one grid ----------------
__global__ void __launch_bounds__(256, 2) fused0_kernel(const float* __restrict__ points2,
                                                        const float* __restrict__ xyz1,
                                                        const float* __restrict__ xyz2) {
    extern __shared__ char dsm[];
    if (blockIdx.x < 256) {
        gemm_body<0>(nullptr, points2,
                     (int)(blockIdx.x & 127) * 128, (int)(blockIdx.x >> 7) * 128, dsm);
    } else {
        knn_body(xyz1, xyz2, (int)blockIdx.x - 256, dsm);
    }
}

template<int EPI>
__global__ void __launch_bounds__(256, 2) gemm_mma_kernel(float* __restrict__ outp,
                                                          const float* __restrict__ Asrc) {
    extern __shared__ char dsm[];
    gemm_body<EPI>(outp, Asrc, (int)blockIdx.x * 128, (int)blockIdx.y * 128, dsm);
}

// ---------------- fold BN into scale/shift -----------------------------------
__global__ void finalize_kernel(const float* __restrict__ gamma,
                                const float* __restrict__ beta, int which) {
    const int t = threadIdx.x;
    const float invM = 1.0f / (float)BNROWS;
    if (which == 0) {
        if (t < C1C) {
            float mean = g_sum1[t] * invM;
            float var  = g_sq1[t] * invM - mean * mean;
            float a    = gamma[t] * rsqrtf(var + EPS_BN);
            g_scale1[t] = a;
            g_shift1[t] = fmaf(-mean, a, beta[t]);
        }
    } else {
        if (t < C2C) {
            float mean = g_sum2[t] * invM;
            float var  = g_sq2[t] * invM - mean * mean;
            float a    = gamma[t] * rsqrtf(var + EPS_BN);
            g_scale2[t] = a;
            g_shift2[t] = fmaf(-mean, a, beta[t]);
        }
    }
}

// ---------------- out = relu(bn2(out)) in place ------------------------------
__global__ void apply_kernel(float* __restrict__ out) {
    const int i = blockIdx.x * blockDim.x + threadIdx.x;   // float4 index
    float4 v = ((float4*)out)[i];
    const int c = (i * 4) & (C2C - 1);
    v.x = fmaxf(fmaf(v.x, g_scale2[c + 0], g_shift2[c + 0]), 0.f);
    v.y = fmaxf(fmaf(v.y, g_scale2[c + 1], g_shift2[c + 1]), 0.f);
    v.z = fmaxf(fmaf(v.z, g_scale2[c + 2], g_shift2[c + 2]), 0.f);
    v.w = fmaxf(fmaf(v.w, g_scale2[c + 3], g_shift2[c + 3]), 0.f);
    ((float4*)out)[i] = v;
}

// ---------------- launch -----------------------------------------------------
extern "C" void kernel_launch(void* const* d_in, const int* in_sizes, int n_in,
                              void* d_out, int out_size) {
    const float* xyz1    = (const float*)d_in[0];
    const float* xyz2    = (const float*)d_in[1];
    const float* points1 = (const float*)d_in[2];
    const float* points2 = (const float*)d_in[3];
    const float* W1      = (const float*)d_in[4];
    const float* g1      = (const float*)d_in[5];
    const float* b1      = (const float*)d_in[6];
    const float* W2      = (const float*)d_in[7];
    const float* g2      = (const float*)d_in[8];
    const float* b2      = (const float*)d_in[9];
    float* out = (float*)d_out;
    (void)in_sizes; (void)n_in; (void)out_size;

    float* h1p;
    cudaGetSymbolAddress((void**)&h1p, g_h1);

    cudaFuncSetAttribute(fused0_kernel,      cudaFuncAttributeMaxDynamicSharedMemorySize, SMEM_GEMM);
    cudaFuncSetAttribute(gemm_mma_kernel<1>, cudaFuncAttributeMaxDynamicSharedMemorySize, SMEM_GEMM);
    cudaFuncSetAttribute(gemm_mma_kernel<2>, cudaFuncAttributeMaxDynamicSharedMemorySize, SMEM_GEMM2);

    prep_kernel<<<57, 256>>>(W1, W2);                                        // 0
    fused0_kernel<<<512, 256, SMEM_GEMM>>>(points2, xyz1, xyz2);             // 1 (gemm0 + knn)
    gemm_mma_kernel<1><<<dim3(BNROWS/128, C1C/128), 256, SMEM_GEMM>>>(nullptr, points1); // 2 (+stats1)
    finalize_kernel<<<1, 256>>>(g1, b1, 0);                                  // 3
    gemm_mma_kernel<2><<<dim3(BNROWS/128, C2C/128), 256, SMEM_GEMM2>>>(out, h1p); // 4 (fused BN1 load, +stats2)
    finalize_kernel<<<1, 256>>>(g2, b2, 1);                                  // 5
    apply_kernel<<<(BNROWS * C2C / 4) / 256, 256>>>(out);                    // 6
}